// round 14
// baseline (speedup 1.0000x reference)
#include <cuda_runtime.h>
#include <cuda_fp16.h>
#include <cstdint>

// VQ argmin via HMMA, 2-way fp16 split, 3 products (hh, lh, hl).
// B pre-shuffled into mma-fragment order in global memory; main loop does all
// 8 fragment LDG.128s per 16-code group up front (MLP=8), then 48 MMAs.
// Schedule: 592 full tiles + 432 split tiles in (24,20,20) group ranges.

#define DIM 64
#define KCODES 1024
#define NROWS (256*512)
#define ROWS_PER_CTA 128
#define THREADS 128
#define NGROUP 64                      // 16 codes per group

#define NTILES (NROWS / ROWS_PER_CTA)  // 1024
#define NBIG 592
#define NSPLIT (NTILES - NBIG)         // 432
#define GRID (NBIG + 3 * NSPLIT)       // 1888

#define SM_C 0
#define SM_IDX 4096
#define SM_TOTAL (SM_IDX + ROWS_PER_CTA * 4)   // 4608

// ---------------- device scratch ----------------
// fragment-ordered B: index (g*4+kt)*32 + lane, 4 regs per lane (uint4)
__device__ uint4 g_fragH[NGROUP * 4 * 32];
__device__ uint4 g_fragL[NGROUP * 4 * 32];
__device__ float g_c[KCODES];
__device__ unsigned long long g_key[NSPLIT * ROWS_PER_CTA];
__device__ unsigned int g_ctr[NSPLIT];

// ---------------- asm helpers ----------------
__device__ __forceinline__ void mma16816(float* d, const uint32_t* a, const uint32_t* b) {
    asm volatile(
        "mma.sync.aligned.m16n8k16.row.col.f32.f16.f16.f32 "
        "{%0,%1,%2,%3}, {%4,%5,%6,%7}, {%8,%9}, {%0,%1,%2,%3};"
        : "+f"(d[0]), "+f"(d[1]), "+f"(d[2]), "+f"(d[3])
        : "r"(a[0]), "r"(a[1]), "r"(a[2]), "r"(a[3]), "r"(b[0]), "r"(b[1]));
}
__device__ __forceinline__ void splitf2(float2 v, uint32_t& hh, uint32_t& ll) {
    __half hx = __float2half_rn(v.x);
    __half hy = __float2half_rn(v.y);
    __half lx = __float2half_rn(v.x - __half2float(hx));
    __half ly = __float2half_rn(v.y - __half2float(hy));
    __half2 H = __halves2half2(hx, hy);
    __half2 L = __halves2half2(lx, ly);
    hh = *(uint32_t*)&H;
    ll = *(uint32_t*)&L;
}
__device__ __forceinline__ uint32_t ordf(float f) {
    uint32_t u = __float_as_uint(f);
    return (u & 0x80000000u) ? ~u : (u | 0x80000000u);
}

// ---------------- fused prep ----------------
#define PREP_CSUM 64
#define PREP_FRAG 32
#define PREP_GRID (PREP_CSUM + PREP_FRAG + NSPLIT)

__global__ void prep_all(const float* __restrict__ emb) {
    const int wid = threadIdx.x >> 5;
    const int lane = threadIdx.x & 31;
    if (blockIdx.x < PREP_CSUM) {
        const int code = blockIdx.x * 16 + wid * 2 + (lane >> 4);
        const int seg = lane & 15;
        float4 v = ((const float4*)(emb + (size_t)code * DIM))[seg];
        float c = v.x * v.x + v.y * v.y + v.z * v.z + v.w * v.w;
#pragma unroll
        for (int off = 8; off; off >>= 1) c += __shfl_down_sync(0xffffffffu, c, off, 16);
        if (seg == 0) g_c[code] = c;
    } else if (blockIdx.x < PREP_CSUM + PREP_FRAG) {
        const int t = (blockIdx.x - PREP_CSUM) * 8 + wid;   // (g, kt) task
        const int g = t >> 2;
        const int kt = t & 3;
        uint32_t h[4], l[4];
#pragma unroll
        for (int i = 0; i < 4; i++) {
            const int code = g * 16 + 8 * (i >> 1) + (lane >> 2);
            const int k = kt * 16 + (i & 1) * 8 + 2 * (lane & 3);
            float2 e = *(const float2*)(emb + (size_t)code * DIM + k);
            splitf2(make_float2(-2.f * e.x, -2.f * e.y), h[i], l[i]);
        }
        const int idx = (g * 4 + kt) * 32 + lane;
        g_fragH[idx] = make_uint4(h[0], h[1], h[2], h[3]);
        g_fragL[idx] = make_uint4(l[0], l[1], l[2], l[3]);
    } else {
        const int sb = blockIdx.x - PREP_CSUM - PREP_FRAG;
        if (threadIdx.x < ROWS_PER_CTA)
            g_key[sb * ROWS_PER_CTA + threadIdx.x] = 0xFFFFFFFFFFFFFFFFull;
        if (threadIdx.x == 0) g_ctr[sb] = 0;
    }
}

// ---------------- main kernel ----------------
__device__ __forceinline__ void row_epilogue(
    int row, int widx,
    const float* __restrict__ inputs, const float* __restrict__ emb,
    float* __restrict__ out_q, float* __restrict__ out_idx, float* __restrict__ out_loss) {
    const float4* e4 = (const float4*)(emb + (size_t)widx * DIM);
    const float4* x4 = (const float4*)(inputs + (size_t)row * DIM);
    float4* o4 = (float4*)(out_q + (size_t)row * DIM);
    float loss = 0.f;
#pragma unroll
    for (int j = 0; j < 16; j++) {
        float4 xv = x4[j];
        float4 ev = e4[j];
        float dx = ev.x - xv.x, dy = ev.y - xv.y;
        float dz = ev.z - xv.z, dw = ev.w - xv.w;
        loss += dx * dx + dy * dy + dz * dz + dw * dw;
        o4[j] = make_float4(xv.x + dx, xv.y + dy, xv.z + dz, xv.w + dw);
    }
    out_idx[row] = (float)widx;
    out_loss[row] = 1.25f * loss;
}

__global__ __launch_bounds__(THREADS, 4)
void vq_main(const float* __restrict__ inputs,
             const float* __restrict__ emb,
             float* __restrict__ out_q,
             float* __restrict__ out_idx,
             float* __restrict__ out_loss) {
    extern __shared__ __align__(16) char smem[];
    const int tid = threadIdx.x;
    const int wid = tid >> 5;
    const int lane = tid & 31;
    const int q = lane & 3;
    const int kq = 2 * q;
    const int lr = lane >> 2;

    const int b = blockIdx.x;
    int tile, g0, g1;
    bool is_split;
    if (b < NBIG) {
        tile = b; g0 = 0; g1 = NGROUP; is_split = false;
    } else {
        const int p = b - NBIG;
        const int cls = p / NSPLIT;
        const int st = p - cls * NSPLIT;
        tile = NBIG + st;
        is_split = true;
        g0 = (cls == 0) ? 0 : (cls == 1 ? 24 : 44);
        g1 = (cls == 0) ? 24 : (cls == 1 ? 44 : 64);
    }

    float* s_c = (float*)(smem + SM_C);
    int* s_idx = (int*)(smem + SM_IDX);

#pragma unroll
    for (int i = tid; i < KCODES; i += THREADS) s_c[i] = g_c[i];

    // A fragments from fp32 inputs, converted in registers
    uint32_t ah[2][4][4], al[2][4][4];
    {
        const int row0 = tile * ROWS_PER_CTA + wid * 32 + lr;
#pragma unroll
        for (int mt = 0; mt < 2; mt++) {
#pragma unroll
            for (int kt = 0; kt < 4; kt++) {
                size_t base = (size_t)(row0 + mt * 16) * DIM + kt * 16 + kq;
                splitf2(*(const float2*)(inputs + base),               ah[mt][kt][0], al[mt][kt][0]);
                splitf2(*(const float2*)(inputs + base + 8 * DIM),     ah[mt][kt][1], al[mt][kt][1]);
                splitf2(*(const float2*)(inputs + base + 8),           ah[mt][kt][2], al[mt][kt][2]);
                splitf2(*(const float2*)(inputs + base + 8 * DIM + 8), ah[mt][kt][3], al[mt][kt][3]);
            }
        }
    }
    __syncthreads();   // s_c ready

    float best[4] = {3.4e38f, 3.4e38f, 3.4e38f, 3.4e38f};
    int bidx[4] = {0, 0, 0, 0};

    // running fragment pointers (one IADD per group)
    const uint4* pH = g_fragH + (size_t)g0 * 4 * 32 + lane;
    const uint4* pL = g_fragL + (size_t)g0 * 4 * 32 + lane;

#pragma unroll 1
    for (int g = g0; g < g1; g++) {
        // all 8 fragment loads up front (MLP = 8)
        uint32_t bfh[4][4], bfl[4][4];
#pragma unroll
        for (int kt = 0; kt < 4; kt++) {
            uint4 v = pH[kt * 32];
            bfh[kt][0] = v.x; bfh[kt][1] = v.y; bfh[kt][2] = v.z; bfh[kt][3] = v.w;
        }
#pragma unroll
        for (int kt = 0; kt < 4; kt++) {
            uint4 v = pL[kt * 32];
            bfl[kt][0] = v.x; bfl[kt][1] = v.y; bfl[kt][2] = v.z; bfl[kt][3] = v.w;
        }
        pH += 4 * 32;
        pL += 4 * 32;

        float acc[2][2][4];
        const int kb0 = g * 16;
        {
            float cc00 = s_c[kb0 + kq];
            float cc01 = s_c[kb0 + kq + 1];
            float cc10 = s_c[kb0 + 8 + kq];
            float cc11 = s_c[kb0 + 8 + kq + 1];
#pragma unroll
            for (int mt = 0; mt < 2; mt++) {
                acc[0][mt][0] = cc00; acc[0][mt][1] = cc01;
                acc[0][mt][2] = cc00; acc[0][mt][3] = cc01;
                acc[1][mt][0] = cc10; acc[1][mt][1] = cc11;
                acc[1][mt][2] = cc10; acc[1][mt][3] = cc11;
            }
        }

        // hh + lh products (b_h), then hl (b_l)
#pragma unroll
        for (int kt = 0; kt < 4; kt++)
#pragma unroll
            for (int half = 0; half < 2; half++)
#pragma unroll
                for (int mt = 0; mt < 2; mt++)
                    mma16816(acc[half][mt], ah[mt][kt], &bfh[kt][2 * half]);
#pragma unroll
        for (int kt = 0; kt < 4; kt++)
#pragma unroll
            for (int half = 0; half < 2; half++)
#pragma unroll
                for (int mt = 0; mt < 2; mt++)
                    mma16816(acc[half][mt], al[mt][kt], &bfh[kt][2 * half]);
#pragma unroll
        for (int kt = 0; kt < 4; kt++)
#pragma unroll
            for (int half = 0; half < 2; half++)
#pragma unroll
                for (int mt = 0; mt < 2; mt++)
                    mma16816(acc[half][mt], ah[mt][kt], &bfl[kt][2 * half]);

        // argmin: 4-way fminf tree per slot
#pragma unroll
        for (int mt = 0; mt < 2; mt++) {
#pragma unroll
            for (int h2 = 0; h2 < 2; h2++) {
                const int slot = mt * 2 + h2;
                float s0 = acc[0][mt][h2 * 2 + 0];
                float s1 = acc[0][mt][h2 * 2 + 1];
                float s2 = acc[1][mt][h2 * 2 + 0];
                float s3 = acc[1][mt][h2 * 2 + 1];
                float m01 = fminf(s0, s1);
                float m23 = fminf(s2, s3);
                float m = fminf(m01, m23);
                if (m < best[slot]) {
                    int i01 = kb0 + kq + (s1 < s0 ? 1 : 0);
                    int i23 = kb0 + 8 + kq + (s3 < s2 ? 1 : 0);
                    bidx[slot] = (m23 < m01) ? i23 : i01;
                    best[slot] = m;
                }
            }
        }
    }
    __syncthreads();   // protect s_idx reuse below

    // reduce argmin across the 4 lanes of each quad-row
#pragma unroll
    for (int off = 1; off <= 2; off <<= 1) {
#pragma unroll
        for (int s = 0; s < 4; s++) {
            float ob = __shfl_xor_sync(0xffffffffu, best[s], off);
            int oi = __shfl_xor_sync(0xffffffffu, bidx[s], off);
            if (ob < best[s] || (ob == best[s] && oi < bidx[s])) {
                best[s] = ob; bidx[s] = oi;
            }
        }
    }

    if (!is_split) {
        if (q == 0) {
            const int rbase = wid * 32 + lr;
#pragma unroll
            for (int s = 0; s < 4; s++) s_idx[rbase + s * 8] = bidx[s];
        }
        __syncthreads();
        row_epilogue(tile * ROWS_PER_CTA + tid, s_idx[tid],
                     inputs, emb, out_q, out_idx, out_loss);
    } else {
        const int st = tile - NBIG;
        if (q == 0) {
            const int rbase = st * ROWS_PER_CTA + wid * 32 + lr;
#pragma unroll
            for (int s = 0; s < 4; s++) {
                unsigned long long key =
                    ((unsigned long long)ordf(best[s]) << 32) | (unsigned)bidx[s];
                atomicMin(&g_key[rbase + s * 8], key);
            }
        }
        __threadfence();
        __syncthreads();
        if (tid == 0) s_idx[0] = (int)atomicAdd(&g_ctr[st], 1u);
        __syncthreads();
        if (s_idx[0] == 2) {
            __threadfence();
            int widx = (int)(unsigned)(g_key[st * ROWS_PER_CTA + tid] & 0xFFFFFFFFull);
            row_epilogue(tile * ROWS_PER_CTA + tid, widx,
                         inputs, emb, out_q, out_idx, out_loss);
        }
    }
}

// ---------------- launcher ----------------
extern "C" void kernel_launch(void* const* d_in, const int* in_sizes, int n_in,
                              void* d_out, int out_size) {
    const float* inputs = (const float*)d_in[0];
    const float* emb = (const float*)d_in[1];
    float* out = (float*)d_out;

    float* out_q = out;
    float* out_idx = out + (size_t)NROWS * DIM;
    float* out_loss = out_idx + NROWS;

    static bool attr_set = false;
    if (!attr_set) {
        cudaFuncSetAttribute(vq_main, cudaFuncAttributeMaxDynamicSharedMemorySize, SM_TOTAL);
        attr_set = true;
    }

    prep_all<<<PREP_GRID, 256>>>(emb);
    vq_main<<<GRID, THREADS, SM_TOTAL>>>(inputs, emb, out_q, out_idx, out_loss);
}

// round 15
// speedup vs baseline: 1.1062x; 1.1062x over previous
#include <cuda_runtime.h>
#include <cuda_fp16.h>
#include <cstdint>

// VQ argmin via HMMA, 2-way fp16 split, 3 products (hh, lh, hl).
// B pre-shuffled into mma-fragment order in global memory. Main loop is
// software-pipelined: L(g) load hides under the 32 hh/lh MMAs, H(g+1)
// prefetch hides under the 16 hl MMAs + argmin. Ping-pong buffers with
// disjoint live ranges (R14's dual-resident buffers regressed).

#define DIM 64
#define KCODES 1024
#define NROWS (256*512)
#define ROWS_PER_CTA 128
#define THREADS 128
#define NGROUP 64                      // 16 codes per group

#define NTILES (NROWS / ROWS_PER_CTA)  // 1024
#define NBIG 592
#define NSPLIT (NTILES - NBIG)         // 432
#define GRID (NBIG + 3 * NSPLIT)       // 1888
// split-piece group ranges: [0,24), [24,44), [44,64)

#define SM_C 0
#define SM_IDX 4096
#define SM_TOTAL (SM_IDX + ROWS_PER_CTA * 4)   // 4608

// ---------------- device scratch ----------------
// fragment-ordered B: index (g*4+kt)*32 + lane, uint4 per lane.
// +4*32 padding so the pipelined prefetch may harmlessly read one group past.
__device__ uint4 g_fragH[(NGROUP * 4 + 4) * 32];
__device__ uint4 g_fragL[(NGROUP * 4 + 4) * 32];
__device__ float g_c[KCODES];
__device__ unsigned long long g_key[NSPLIT * ROWS_PER_CTA];
__device__ unsigned int g_ctr[NSPLIT];

// ---------------- asm helpers ----------------
__device__ __forceinline__ void mma16816(float* d, const uint32_t* a, const uint32_t* b) {
    asm volatile(
        "mma.sync.aligned.m16n8k16.row.col.f32.f16.f16.f32 "
        "{%0,%1,%2,%3}, {%4,%5,%6,%7}, {%8,%9}, {%0,%1,%2,%3};"
        : "+f"(d[0]), "+f"(d[1]), "+f"(d[2]), "+f"(d[3])
        : "r"(a[0]), "r"(a[1]), "r"(a[2]), "r"(a[3]), "r"(b[0]), "r"(b[1]));
}
__device__ __forceinline__ void splitf2(float2 v, uint32_t& hh, uint32_t& ll) {
    __half hx = __float2half_rn(v.x);
    __half hy = __float2half_rn(v.y);
    __half lx = __float2half_rn(v.x - __half2float(hx));
    __half ly = __float2half_rn(v.y - __half2float(hy));
    __half2 H = __halves2half2(hx, hy);
    __half2 L = __halves2half2(lx, ly);
    hh = *(uint32_t*)&H;
    ll = *(uint32_t*)&L;
}
__device__ __forceinline__ uint32_t ordf(float f) {
    uint32_t u = __float_as_uint(f);
    return (u & 0x80000000u) ? ~u : (u | 0x80000000u);
}
__device__ __forceinline__ void loadfrag(uint32_t bf[4][4], const uint4* p) {
#pragma unroll
    for (int kt = 0; kt < 4; kt++) {
        uint4 v = p[kt * 32];
        bf[kt][0] = v.x; bf[kt][1] = v.y; bf[kt][2] = v.z; bf[kt][3] = v.w;
    }
}

// ---------------- fused prep ----------------
#define PREP_CSUM 64
#define PREP_FRAG 32
#define PREP_GRID (PREP_CSUM + PREP_FRAG + NSPLIT)

__global__ void prep_all(const float* __restrict__ emb) {
    const int wid = threadIdx.x >> 5;
    const int lane = threadIdx.x & 31;
    if (blockIdx.x < PREP_CSUM) {
        const int code = blockIdx.x * 16 + wid * 2 + (lane >> 4);
        const int seg = lane & 15;
        float4 v = ((const float4*)(emb + (size_t)code * DIM))[seg];
        float c = v.x * v.x + v.y * v.y + v.z * v.z + v.w * v.w;
#pragma unroll
        for (int off = 8; off; off >>= 1) c += __shfl_down_sync(0xffffffffu, c, off, 16);
        if (seg == 0) g_c[code] = c;
    } else if (blockIdx.x < PREP_CSUM + PREP_FRAG) {
        const int t = (blockIdx.x - PREP_CSUM) * 8 + wid;   // (g, kt) task
        const int g = t >> 2;
        const int kt = t & 3;
        uint32_t h[4], l[4];
#pragma unroll
        for (int i = 0; i < 4; i++) {
            const int code = g * 16 + 8 * (i >> 1) + (lane >> 2);
            const int k = kt * 16 + (i & 1) * 8 + 2 * (lane & 3);
            float2 e = *(const float2*)(emb + (size_t)code * DIM + k);
            splitf2(make_float2(-2.f * e.x, -2.f * e.y), h[i], l[i]);
        }
        const int idx = (g * 4 + kt) * 32 + lane;
        g_fragH[idx] = make_uint4(h[0], h[1], h[2], h[3]);
        g_fragL[idx] = make_uint4(l[0], l[1], l[2], l[3]);
    } else {
        const int sb = blockIdx.x - PREP_CSUM - PREP_FRAG;
        if (threadIdx.x < ROWS_PER_CTA)
            g_key[sb * ROWS_PER_CTA + threadIdx.x] = 0xFFFFFFFFFFFFFFFFull;
        if (threadIdx.x == 0) g_ctr[sb] = 0;
    }
}

// ---------------- main kernel ----------------
__device__ __forceinline__ void row_epilogue(
    int row, int widx,
    const float* __restrict__ inputs, const float* __restrict__ emb,
    float* __restrict__ out_q, float* __restrict__ out_idx, float* __restrict__ out_loss) {
    const float4* e4 = (const float4*)(emb + (size_t)widx * DIM);
    const float4* x4 = (const float4*)(inputs + (size_t)row * DIM);
    float4* o4 = (float4*)(out_q + (size_t)row * DIM);
    float loss = 0.f;
#pragma unroll
    for (int j = 0; j < 16; j++) {
        float4 xv = x4[j];
        float4 ev = e4[j];
        float dx = ev.x - xv.x, dy = ev.y - xv.y;
        float dz = ev.z - xv.z, dw = ev.w - xv.w;
        loss += dx * dx + dy * dy + dz * dz + dw * dw;
        o4[j] = make_float4(xv.x + dx, xv.y + dy, xv.z + dz, xv.w + dw);
    }
    out_idx[row] = (float)widx;
    out_loss[row] = 1.25f * loss;
}

__global__ __launch_bounds__(THREADS, 4)
void vq_main(const float* __restrict__ inputs,
             const float* __restrict__ emb,
             float* __restrict__ out_q,
             float* __restrict__ out_idx,
             float* __restrict__ out_loss) {
    extern __shared__ __align__(16) char smem[];
    const int tid = threadIdx.x;
    const int wid = tid >> 5;
    const int lane = tid & 31;
    const int q = lane & 3;
    const int kq = 2 * q;
    const int lr = lane >> 2;

    const int b = blockIdx.x;
    int tile, g0, g1;
    bool is_split;
    if (b < NBIG) {
        tile = b; g0 = 0; g1 = NGROUP; is_split = false;
    } else {
        const int p = b - NBIG;
        const int cls = p / NSPLIT;
        const int st = p - cls * NSPLIT;
        tile = NBIG + st;
        is_split = true;
        g0 = (cls == 0) ? 0 : (cls == 1 ? 24 : 44);
        g1 = (cls == 0) ? 24 : (cls == 1 ? 44 : 64);
    }

    float* s_c = (float*)(smem + SM_C);
    int* s_idx = (int*)(smem + SM_IDX);

#pragma unroll
    for (int i = tid; i < KCODES; i += THREADS) s_c[i] = g_c[i];

    // A fragments from fp32 inputs, converted in registers
    uint32_t ah[2][4][4], al[2][4][4];
    {
        const int row0 = tile * ROWS_PER_CTA + wid * 32 + lr;
#pragma unroll
        for (int mt = 0; mt < 2; mt++) {
#pragma unroll
            for (int kt = 0; kt < 4; kt++) {
                size_t base = (size_t)(row0 + mt * 16) * DIM + kt * 16 + kq;
                splitf2(*(const float2*)(inputs + base),               ah[mt][kt][0], al[mt][kt][0]);
                splitf2(*(const float2*)(inputs + base + 8 * DIM),     ah[mt][kt][1], al[mt][kt][1]);
                splitf2(*(const float2*)(inputs + base + 8),           ah[mt][kt][2], al[mt][kt][2]);
                splitf2(*(const float2*)(inputs + base + 8 * DIM + 8), ah[mt][kt][3], al[mt][kt][3]);
            }
        }
    }
    __syncthreads();   // s_c ready

    float best[4] = {3.4e38f, 3.4e38f, 3.4e38f, 3.4e38f};
    int bidx[4] = {0, 0, 0, 0};

    const uint4* pH = g_fragH + (size_t)g0 * 4 * 32 + lane;
    const uint4* pL = g_fragL + (size_t)g0 * 4 * 32 + lane;

    uint32_t bufA[4][4], bufB[4][4];
    loadfrag(bufA, pH);                 // H(g0)
    pH += 4 * 32;

#pragma unroll 1
    for (int g = g0; g < g1; g++) {
        // 1) issue L(g) load; hides under the 32 hh/lh MMAs below
        loadfrag(bufB, pL);
        pL += 4 * 32;

        float acc[2][2][4];
        const int kb0 = g * 16;
        {
            float cc00 = s_c[kb0 + kq];
            float cc01 = s_c[kb0 + kq + 1];
            float cc10 = s_c[kb0 + 8 + kq];
            float cc11 = s_c[kb0 + 8 + kq + 1];
#pragma unroll
            for (int mt = 0; mt < 2; mt++) {
                acc[0][mt][0] = cc00; acc[0][mt][1] = cc01;
                acc[0][mt][2] = cc00; acc[0][mt][3] = cc01;
                acc[1][mt][0] = cc10; acc[1][mt][1] = cc11;
                acc[1][mt][2] = cc10; acc[1][mt][3] = cc11;
            }
        }

        // 2) hh + lh products using bufA = H(g)
#pragma unroll
        for (int kt = 0; kt < 4; kt++)
#pragma unroll
            for (int half = 0; half < 2; half++)
#pragma unroll
                for (int mt = 0; mt < 2; mt++)
                    mma16816(acc[half][mt], ah[mt][kt], &bufA[kt][2 * half]);
#pragma unroll
        for (int kt = 0; kt < 4; kt++)
#pragma unroll
            for (int half = 0; half < 2; half++)
#pragma unroll
                for (int mt = 0; mt < 2; mt++)
                    mma16816(acc[half][mt], al[mt][kt], &bufA[kt][2 * half]);

        // 3) bufA dead -> prefetch H(g+1) (padded array, last read harmless)
        loadfrag(bufA, pH);
        pH += 4 * 32;

        // 4) hl product using bufB = L(g)
#pragma unroll
        for (int kt = 0; kt < 4; kt++)
#pragma unroll
            for (int half = 0; half < 2; half++)
#pragma unroll
                for (int mt = 0; mt < 2; mt++)
                    mma16816(acc[half][mt], ah[mt][kt], &bufB[kt][2 * half]);

        // 5) argmin: 4-way fminf tree per slot (hides H(g+1) latency)
#pragma unroll
        for (int mt = 0; mt < 2; mt++) {
#pragma unroll
            for (int h2 = 0; h2 < 2; h2++) {
                const int slot = mt * 2 + h2;
                float s0 = acc[0][mt][h2 * 2 + 0];
                float s1 = acc[0][mt][h2 * 2 + 1];
                float s2 = acc[1][mt][h2 * 2 + 0];
                float s3 = acc[1][mt][h2 * 2 + 1];
                float m01 = fminf(s0, s1);
                float m23 = fminf(s2, s3);
                float m = fminf(m01, m23);
                if (m < best[slot]) {
                    int i01 = kb0 + kq + (s1 < s0 ? 1 : 0);
                    int i23 = kb0 + 8 + kq + (s3 < s2 ? 1 : 0);
                    bidx[slot] = (m23 < m01) ? i23 : i01;
                    best[slot] = m;
                }
            }
        }
    }
    __syncthreads();   // protect s_idx reuse below

    // reduce argmin across the 4 lanes of each quad-row
#pragma unroll
    for (int off = 1; off <= 2; off <<= 1) {
#pragma unroll
        for (int s = 0; s < 4; s++) {
            float ob = __shfl_xor_sync(0xffffffffu, best[s], off);
            int oi = __shfl_xor_sync(0xffffffffu, bidx[s], off);
            if (ob < best[s] || (ob == best[s] && oi < bidx[s])) {
                best[s] = ob; bidx[s] = oi;
            }
        }
    }

    if (!is_split) {
        if (q == 0) {
            const int rbase = wid * 32 + lr;
#pragma unroll
            for (int s = 0; s < 4; s++) s_idx[rbase + s * 8] = bidx[s];
        }
        __syncthreads();
        row_epilogue(tile * ROWS_PER_CTA + tid, s_idx[tid],
                     inputs, emb, out_q, out_idx, out_loss);
    } else {
        const int st = tile - NBIG;
        if (q == 0) {
            const int rbase = st * ROWS_PER_CTA + wid * 32 + lr;
#pragma unroll
            for (int s = 0; s < 4; s++) {
                unsigned long long key =
                    ((unsigned long long)ordf(best[s]) << 32) | (unsigned)bidx[s];
                atomicMin(&g_key[rbase + s * 8], key);
            }
        }
        __threadfence();
        __syncthreads();
        if (tid == 0) s_idx[0] = (int)atomicAdd(&g_ctr[st], 1u);
        __syncthreads();
        if (s_idx[0] == 2) {
            __threadfence();
            int widx = (int)(unsigned)(g_key[st * ROWS_PER_CTA + tid] & 0xFFFFFFFFull);
            row_epilogue(tile * ROWS_PER_CTA + tid, widx,
                         inputs, emb, out_q, out_idx, out_loss);
        }
    }
}

// ---------------- launcher ----------------
extern "C" void kernel_launch(void* const* d_in, const int* in_sizes, int n_in,
                              void* d_out, int out_size) {
    const float* inputs = (const float*)d_in[0];
    const float* emb = (const float*)d_in[1];
    float* out = (float*)d_out;

    float* out_q = out;
    float* out_idx = out + (size_t)NROWS * DIM;
    float* out_loss = out_idx + NROWS;

    static bool attr_set = false;
    if (!attr_set) {
        cudaFuncSetAttribute(vq_main, cudaFuncAttributeMaxDynamicSharedMemorySize, SM_TOTAL);
        attr_set = true;
    }

    prep_all<<<PREP_GRID, 256>>>(emb);
    vq_main<<<GRID, THREADS, SM_TOTAL>>>(inputs, emb, out_q, out_idx, out_loss);
}